// round 15
// baseline (speedup 1.0000x reference)
#include <cuda_runtime.h>
#include <cuda_bf16.h>
#include <cstdint>
#include <cstring>

// MLP_Interpolate: 4x nearest upsample + 2-layer MLP. SINGLE LAUNCH.
// GEMM1 (base = X @ W1[0:64]^T): tensor pipe, bf16 3-term split (~1.5e-5).
// GEMM2 (out = relu(H) @ W2): tensor pipe, fp16 single-term (~2e-4), H built
// directly in mma A-fragment layout. Output fragments staged in smem
// (padded rows, cheap STS) then stored as 6 coalesced STG.128 per thread —
// removes the 64-scattered-STG.32 store path that made L1 the top pipe (r14).

namespace {

typedef unsigned long long ull;

__device__ __forceinline__ ull pk(float lo, float hi) {
    ull r; asm("mov.b64 %0, {%1, %2};" : "=l"(r) : "f"(lo), "f"(hi)); return r;
}
__device__ __forceinline__ float2 upk(ull a) {
    float2 r; asm("mov.b64 {%0, %1}, %2;" : "=f"(r.x), "=f"(r.y) : "l"(a)); return r;
}
__device__ __forceinline__ ull addx2(ull a, ull b) {
    ull d; asm("add.rn.f32x2 %0, %1, %2;" : "=l"(d) : "l"(a), "l"(b)); return d;
}
__device__ __forceinline__ uint32_t s2u(const void* p) {
    uint32_t a;
    asm("{ .reg .u64 t; cvta.to.shared.u64 t, %1; cvt.u32.u64 %0, t; }" : "=r"(a) : "l"(p));
    return a;
}
// f32x2 pair -> relu'd f16x2 (low element = low half)
__device__ __forceinline__ uint32_t cvt_relu_f16x2(ull t) {
    const float2 v = upk(t);
    uint32_t r;
    asm("cvt.rn.f16x2.f32 %0, %1, %2;" : "=r"(r) : "f"(v.y), "f"(v.x));
    asm("max.f16x2 %0, %0, %1;" : "+r"(r) : "r"(0u));
    return r;
}
__device__ __forceinline__ void ldsm4(uint32_t addr, uint32_t& r0, uint32_t& r1,
                                      uint32_t& r2, uint32_t& r3) {
    asm volatile("ldmatrix.sync.aligned.m8n8.x4.shared.b16 {%0,%1,%2,%3}, [%4];"
                 : "=r"(r0), "=r"(r1), "=r"(r2), "=r"(r3) : "r"(addr));
}
__device__ __forceinline__ void mma_bf16(float* d, const uint32_t* a,
                                         uint32_t b0, uint32_t b1) {
    asm volatile(
        "mma.sync.aligned.m16n8k16.row.col.f32.bf16.bf16.f32 "
        "{%0,%1,%2,%3}, {%4,%5,%6,%7}, {%8,%9}, {%0,%1,%2,%3};"
        : "+f"(d[0]), "+f"(d[1]), "+f"(d[2]), "+f"(d[3])
        : "r"(a[0]), "r"(a[1]), "r"(a[2]), "r"(a[3]), "r"(b0), "r"(b1));
}
__device__ __forceinline__ void mma_f16(float* d, const uint32_t* a,
                                        uint32_t b0, uint32_t b1) {
    asm volatile(
        "mma.sync.aligned.m16n8k16.row.col.f32.f16.f16.f32 "
        "{%0,%1,%2,%3}, {%4,%5,%6,%7}, {%8,%9}, {%0,%1,%2,%3};"
        : "+f"(d[0]), "+f"(d[1]), "+f"(d[2]), "+f"(d[3])
        : "r"(a[0]), "r"(a[1]), "r"(a[2]), "r"(a[3]), "r"(b0), "r"(b1));
}

constexpr int Hh = 128, Wd = 128, HW = Hh * Wd, OUT = 512;
constexpr int BSTR = 68;   // base_s row stride (floats); 272 B
constexpr int OSTR = 516;  // out_s row stride (floats); 2064 B, 16B-aligned

// smem layout (bytes).
// Staging phase: A (0..32768), B (32768..49152), ET (59584..60608).
// Post-GEMM1:    base_s (0..34816), out_s (34816..59584) overlay dead A/B.
constexpr int S_AHI = 0;            // X_hi  [128][64 bf16]  16384
constexpr int S_ALO = 16384;        // X_lo                  16384
constexpr int S_BHI = 32768;        // W1T_hi [64][64 bf16]   8192
constexpr int S_BLO = 40960;        // W1T_lo                 8192
constexpr int S_OUT = 34816;        // out_s [12][516] f32   24768
constexpr int S_ET  = 59584;        // ET4[64] float4 {u,v,b1,0} 1024
constexpr int S_TOTAL = 60608;

// split 8 floats -> bf16-hi quad + bf16-lo quad
__device__ __forceinline__ void pack8(const float* v, uint4& qh, uint4& ql) {
    uint32_t H[4], L[4];
    #pragma unroll
    for (int p = 0; p < 4; p++) {
        uint32_t hp;
        asm("cvt.rn.bf16x2.f32 %0, %1, %2;" : "=r"(hp) : "f"(v[2*p+1]), "f"(v[2*p]));
        const float h0 = __uint_as_float(hp << 16);
        const float h1 = __uint_as_float(hp & 0xffff0000u);
        const float l0 = v[2*p]   - h0;
        const float l1 = v[2*p+1] - h1;
        uint32_t lp;
        asm("cvt.rn.bf16x2.f32 %0, %1, %2;" : "=r"(lp) : "f"(l1), "f"(l0));
        H[p] = hp; L[p] = lp;
    }
    qh = make_uint4(H[0], H[1], H[2], H[3]);
    ql = make_uint4(L[0], L[1], L[2], L[3]);
}

__global__ __launch_bounds__(256, 3)
void mlp_interp_mma(const float* __restrict__ x, const float* __restrict__ W1,
                    const float* __restrict__ b1, const float* __restrict__ W2,
                    const float* __restrict__ b2, float* __restrict__ out)
{
    extern __shared__ char smem[];
    const uint32_t sb = s2u(smem);
    const int tid  = threadIdx.x;
    const int lane = tid & 31;
    const int wid  = tid >> 5;            // 0..7
    const int pxs  = tid >> 1;            // staging pixel 0..127
    const int shalf = tid & 1;            // staging channel half
    const int cta  = blockIdx.x;          // 512: (b, h)
    const int h = cta & (Hh - 1);
    const int b = cta >> 7;

    // ---- stage A: thread (pxs, shalf) packs channels [32s, 32s+32) ----
    {
        const float* xp = x + ((size_t)b * 64 + 32 * shalf) * HW + h * Wd + pxs;
        #pragma unroll
        for (int qq = 0; qq < 4; qq++) {
            float v[8];
            #pragma unroll
            for (int c = 0; c < 8; c++) v[c] = xp[(size_t)(8 * qq + c) * HW];
            uint4 qhv, qlv;
            pack8(v, qhv, qlv);
            const int q = 4 * shalf + qq;
            const uint32_t off = (uint32_t)pxs * 128 + (uint32_t)((q ^ (pxs & 7)) << 4);
            *(uint4*)(smem + S_AHI + off) = qhv;
            *(uint4*)(smem + S_ALO + off) = qlv;
        }
    }

    if (tid >= 128) {
        // ---- stage B: thread (i, s2) packs W1[32s2..32s2+32][i] ----
        const int t2 = tid - 128;
        const int i  = t2 >> 1;
        const int s2 = t2 & 1;
        #pragma unroll
        for (int qq = 0; qq < 4; qq++) {
            float v[8];
            #pragma unroll
            for (int c = 0; c < 8; c++) v[c] = W1[(32 * s2 + 8 * qq + c) * 64 + i];
            uint4 qhv, qlv;
            pack8(v, qhv, qlv);
            const int q = 4 * s2 + qq;
            const uint32_t off = (uint32_t)i * 128 + (uint32_t)((q ^ (i & 7)) << 4);
            *(uint4*)(smem + S_BHI + off) = qhv;
            *(uint4*)(smem + S_BLO + off) = qlv;
        }
    } else if (tid < 64) {
        // ---- ET table: {u_i, v_i, b1_i, 0} ----
        const int c = tid;
        ((float4*)(smem + S_ET))[c] =
            make_float4(W1[64 * 64 + c], W1[64 * 64 + 64 + c], b1[c], 0.f);
    }
    __syncthreads();

    // ---- GEMM1: warp wid owns pixel rows [16*wid, 16*wid+16) ----
    float dacc[8][4];
    #pragma unroll
    for (int nt = 0; nt < 8; nt++)
        #pragma unroll
        for (int r = 0; r < 4; r++) dacc[nt][r] = 0.f;

    {
        const int m0w = 16 * wid;
        const int rl  = lane & 15;
        const int qhh = lane >> 4;
        const int rx  = lane & 7;

        #pragma unroll
        for (int term = 0; term < 3; term++) {
            const uint32_t SA = sb + (term == 1 ? S_ALO : S_AHI);
            const uint32_t SB = sb + (term == 2 ? S_BLO : S_BHI);
            #pragma unroll
            for (int kt = 0; kt < 4; kt++) {
                const uint32_t kx = (uint32_t)(((2 * kt + qhh) ^ rx) << 4);
                uint32_t a0[4];
                ldsm4(SA + (uint32_t)(m0w + rl) * 128 + kx, a0[0], a0[1], a0[2], a0[3]);
                #pragma unroll
                for (int ntp = 0; ntp < 4; ntp++) {
                    uint32_t r0, r1, r2, r3;
                    ldsm4(SB + (uint32_t)(16 * ntp + rl) * 128 + kx, r0, r1, r2, r3);
                    mma_bf16(dacc[2 * ntp],     a0, r0, r2);
                    mma_bf16(dacc[2 * ntp + 1], a0, r1, r3);
                }
            }
        }
    }
    __syncthreads();   // all ldmatrix reads done before base_s overwrites A/B

    // ---- D fragments -> base_s[px][i] ----
    float* base_s = (float*)smem;
    {
        const int g = lane >> 2, tg0 = lane & 3;
        const int m = 16 * wid + g;
        #pragma unroll
        for (int nt = 0; nt < 8; nt++) {
            const int col = nt * 8 + 2 * tg0;
            *(float2*)(base_s + m * BSTR + col) =
                make_float2(dacc[nt][0], dacc[nt][1]);
            *(float2*)(base_s + (m + 8) * BSTR + col) =
                make_float2(dacc[nt][2], dacc[nt][3]);
        }
    }
    __syncthreads();

    // ==== GEMM2: per px, out[16 jk, 8ch] = relu(H)[16,64] @ W2 ====
    const int tg   = lane & 3;
    const int row0 = lane >> 2;            // jk row (j = row>>2, k = row&3)
    const int j0   = row0 >> 2;
    const int k0i  = row0 & 3;
    const float rj = -0.75f + 0.5f * (float)j0;
    const float rk = -0.75f + 0.5f * (float)k0i;

    // per-thread ajbk constants for my 16 i-cols (pairs), rows row0 / row0+8
    const float4* ET4 = (const float4*)(smem + S_ET);
    ull ajbk0[8], ajbk1[8];
    #pragma unroll
    for (int p = 0; p < 8; p++) {
        const int i0 = (p >> 1) * 16 + (p & 1) * 8 + 2 * tg;
        const float4 ea = ET4[i0];
        const float4 eb = ET4[i0 + 1];
        const float f0 = fmaf(rj, ea.x, fmaf(rk, ea.y, ea.z));
        const float f1 = fmaf(rj, eb.x, fmaf(rk, eb.y, eb.z));
        ajbk0[p] = pk(f0, f1);                       // row0
        ajbk1[p] = pk(f0 + ea.x, f1 + eb.x);         // row0+8 (j+2 -> rel+1)
    }

    // W2 fp16 B-fragments (col n = lane>>2; valid n < 3)
    const int nn = lane >> 2;
    const bool nv = nn < 3;
    uint32_t bw[4][2];
    #pragma unroll
    for (int kt = 0; kt < 4; kt++) {
        #pragma unroll
        for (int hh = 0; hh < 2; hh++) {
            const int kk = kt * 16 + 2 * tg + hh * 8;
            const float w0 = nv ? W2[kk * 3 + nn] : 0.f;
            const float w1 = nv ? W2[(kk + 1) * 3 + nn] : 0.f;
            asm("cvt.rn.f16x2.f32 %0, %1, %2;" : "=r"(bw[kt][hh]) : "f"(w1), "f"(w0));
        }
    }

    const int ch0 = 2 * tg, ch1 = 2 * tg + 1;
    const float bb0 = (ch0 < 3) ? b2[ch0] : 0.f;
    const float bb1 = (ch1 < 3) ? b2[ch1] : 0.f;

    float* out_s = (float*)(smem + S_OUT);

    #pragma unroll 2
    for (int t16 = 0; t16 < 16; t16++) {
        const int px = 16 * wid + t16;
        const ull* bprow = (const ull*)(base_s + px * BSTR);
        float C[4] = {0.f, 0.f, 0.f, 0.f};
        #pragma unroll
        for (int kt = 0; kt < 4; kt++) {
            uint32_t a[4];
            {
                const ull bp = bprow[kt * 8 + tg];
                a[0] = cvt_relu_f16x2(addx2(bp, ajbk0[kt * 2]));
                a[1] = cvt_relu_f16x2(addx2(bp, ajbk1[kt * 2]));
            }
            {
                const ull bp = bprow[kt * 8 + 4 + tg];
                a[2] = cvt_relu_f16x2(addx2(bp, ajbk0[kt * 2 + 1]));
                a[3] = cvt_relu_f16x2(addx2(bp, ajbk1[kt * 2 + 1]));
            }
            mma_f16(C, a, bw[kt][0], bw[kt][1]);
        }
        // stage to smem: rows (ch*4 + j), col 4*px + k0i
        const int xx = 4 * px + k0i;
        if (ch0 < 3) {
            out_s[(ch0 * 4 + j0) * OSTR + xx]       = C[0] + bb0;
            out_s[(ch0 * 4 + j0 + 2) * OSTR + xx]   = C[2] + bb0;
        }
        if (ch1 < 3) {
            out_s[(ch1 * 4 + j0) * OSTR + xx]       = C[1] + bb1;
            out_s[(ch1 * 4 + j0 + 2) * OSTR + xx]   = C[3] + bb1;
        }
    }
    __syncthreads();

    // ---- coalesced store-out: 12 rows x 512 floats = 1536 float4 ----
    float4* op = (float4*)out;
    #pragma unroll
    for (int r = 0; r < 6; r++) {
        const int idx = r * 256 + tid;        // 0..1535
        const int row = idx >> 7;             // ch*4 + j
        const int c4  = idx & 127;
        const int ch = row >> 2, j = row & 3;
        const float4 v = *(const float4*)(out_s + row * OSTR + 4 * c4);
        op[((size_t)(b * 3 + ch) * OUT + 4 * h + j) * (OUT / 4) + c4] = v;
    }
}

}  // namespace

extern "C" void kernel_launch(void* const* d_in, const int* in_sizes, int n_in,
                              void* d_out, int out_size) {
    const float* x  = (const float*)d_in[0];
    const float* W1 = (const float*)d_in[1];
    const float* b1 = (const float*)d_in[2];
    const float* W2 = (const float*)d_in[3];
    const float* b2 = (const float*)d_in[4];
    float* out = (float*)d_out;

    cudaFuncSetAttribute(mlp_interp_mma,
                         cudaFuncAttributeMaxDynamicSharedMemorySize, S_TOTAL);
    mlp_interp_mma<<<512, 256, S_TOTAL>>>(x, W1, b1, W2, b2, out);
}

// round 16
// speedup vs baseline: 1.1043x; 1.1043x over previous
#include <cuda_runtime.h>
#include <cuda_bf16.h>
#include <cstdint>
#include <cstring>

// MLP_Interpolate: 4x nearest upsample + 2-layer MLP. SINGLE LAUNCH.
// GEMM1 (base = X @ W1[0:64]^T): tensor pipe, bf16 3-term split (~1.5e-5).
// GEMM2 (out = relu(H) @ W2): tensor pipe fp16. H carried in fp16 end-to-end:
// base converted f32->f16x2 ONCE at the transpose, ajbk constants pre-built
// as f16x2, so the hot loop is LDS.32 -> add.f16x2 -> max.f16x2 -> mma
// (no cvt; chain 60->37 cyc; ~320 fewer instrs/thread vs r14).

namespace {

typedef unsigned long long ull;

__device__ __forceinline__ uint32_t s2u(const void* p) {
    uint32_t a;
    asm("{ .reg .u64 t; cvta.to.shared.u64 t, %1; cvt.u32.u64 %0, t; }" : "=r"(a) : "l"(p));
    return a;
}
__device__ __forceinline__ uint32_t f16x2of(float lo, float hi) {
    uint32_t r;
    asm("cvt.rn.f16x2.f32 %0, %1, %2;" : "=r"(r) : "f"(hi), "f"(lo));
    return r;
}
__device__ __forceinline__ uint32_t hadd2(uint32_t a, uint32_t b) {
    uint32_t d; asm("add.rn.f16x2 %0, %1, %2;" : "=r"(d) : "r"(a), "r"(b)); return d;
}
__device__ __forceinline__ uint32_t hmax2z(uint32_t a) {
    uint32_t d; asm("max.f16x2 %0, %1, %2;" : "=r"(d) : "r"(a), "r"(0u)); return d;
}
__device__ __forceinline__ void ldsm4(uint32_t addr, uint32_t& r0, uint32_t& r1,
                                      uint32_t& r2, uint32_t& r3) {
    asm volatile("ldmatrix.sync.aligned.m8n8.x4.shared.b16 {%0,%1,%2,%3}, [%4];"
                 : "=r"(r0), "=r"(r1), "=r"(r2), "=r"(r3) : "r"(addr));
}
__device__ __forceinline__ void mma_bf16(float* d, const uint32_t* a,
                                         uint32_t b0, uint32_t b1) {
    asm volatile(
        "mma.sync.aligned.m16n8k16.row.col.f32.bf16.bf16.f32 "
        "{%0,%1,%2,%3}, {%4,%5,%6,%7}, {%8,%9}, {%0,%1,%2,%3};"
        : "+f"(d[0]), "+f"(d[1]), "+f"(d[2]), "+f"(d[3])
        : "r"(a[0]), "r"(a[1]), "r"(a[2]), "r"(a[3]), "r"(b0), "r"(b1));
}
__device__ __forceinline__ void mma_f16(float* d, const uint32_t* a,
                                        uint32_t b0, uint32_t b1) {
    asm volatile(
        "mma.sync.aligned.m16n8k16.row.col.f32.f16.f16.f32 "
        "{%0,%1,%2,%3}, {%4,%5,%6,%7}, {%8,%9}, {%0,%1,%2,%3};"
        : "+f"(d[0]), "+f"(d[1]), "+f"(d[2]), "+f"(d[3])
        : "r"(a[0]), "r"(a[1]), "r"(a[2]), "r"(a[3]), "r"(b0), "r"(b1));
}

constexpr int Hh = 128, Wd = 128, HW = Hh * Wd, OUT = 512;
constexpr int HSTR = 34;   // base16_s row stride in uint32 (f16x2 pairs); 136 B

// smem layout (bytes).
// Staging: A (0..32768), B (32768..49152), ET (49152..50176).
// Post-GEMM1: base16_s [128][34] uint32 (17408 B) overlays dead A region.
constexpr int S_AHI = 0;            // X_hi  [128][64 bf16]  16384
constexpr int S_ALO = 16384;        // X_lo                  16384
constexpr int S_BHI = 32768;        // W1T_hi [64][64 bf16]   8192
constexpr int S_BLO = 40960;        // W1T_lo                 8192
constexpr int S_ET  = 49152;        // ET4[64] float4 {u,v,b1,0} 1024
constexpr int S_TOTAL = 50176;

// split 8 floats -> bf16-hi quad + bf16-lo quad
__device__ __forceinline__ void pack8(const float* v, uint4& qh, uint4& ql) {
    uint32_t H[4], L[4];
    #pragma unroll
    for (int p = 0; p < 4; p++) {
        uint32_t hp;
        asm("cvt.rn.bf16x2.f32 %0, %1, %2;" : "=r"(hp) : "f"(v[2*p+1]), "f"(v[2*p]));
        const float h0 = __uint_as_float(hp << 16);
        const float h1 = __uint_as_float(hp & 0xffff0000u);
        const float l0 = v[2*p]   - h0;
        const float l1 = v[2*p+1] - h1;
        uint32_t lp;
        asm("cvt.rn.bf16x2.f32 %0, %1, %2;" : "=r"(lp) : "f"(l1), "f"(l0));
        H[p] = hp; L[p] = lp;
    }
    qh = make_uint4(H[0], H[1], H[2], H[3]);
    ql = make_uint4(L[0], L[1], L[2], L[3]);
}

__global__ __launch_bounds__(256, 3)
void mlp_interp_mma(const float* __restrict__ x, const float* __restrict__ W1,
                    const float* __restrict__ b1, const float* __restrict__ W2,
                    const float* __restrict__ b2, float* __restrict__ out)
{
    extern __shared__ char smem[];
    const uint32_t sb = s2u(smem);
    const int tid  = threadIdx.x;
    const int lane = tid & 31;
    const int wid  = tid >> 5;            // 0..7
    const int pxs  = tid >> 1;            // staging pixel 0..127
    const int shalf = tid & 1;            // staging channel half
    const int cta  = blockIdx.x;          // 512: (b, h)
    const int h = cta & (Hh - 1);
    const int b = cta >> 7;

    // ---- stage A: thread (pxs, shalf) packs channels [32s, 32s+32) ----
    {
        const float* xp = x + ((size_t)b * 64 + 32 * shalf) * HW + h * Wd + pxs;
        #pragma unroll
        for (int qq = 0; qq < 4; qq++) {
            float v[8];
            #pragma unroll
            for (int c = 0; c < 8; c++) v[c] = xp[(size_t)(8 * qq + c) * HW];
            uint4 qhv, qlv;
            pack8(v, qhv, qlv);
            const int q = 4 * shalf + qq;
            const uint32_t off = (uint32_t)pxs * 128 + (uint32_t)((q ^ (pxs & 7)) << 4);
            *(uint4*)(smem + S_AHI + off) = qhv;
            *(uint4*)(smem + S_ALO + off) = qlv;
        }
    }

    if (tid >= 128) {
        // ---- stage B: thread (i, s2) packs W1[32s2..32s2+32][i] ----
        const int t2 = tid - 128;
        const int i  = t2 >> 1;
        const int s2 = t2 & 1;
        #pragma unroll
        for (int qq = 0; qq < 4; qq++) {
            float v[8];
            #pragma unroll
            for (int c = 0; c < 8; c++) v[c] = W1[(32 * s2 + 8 * qq + c) * 64 + i];
            uint4 qhv, qlv;
            pack8(v, qhv, qlv);
            const int q = 4 * s2 + qq;
            const uint32_t off = (uint32_t)i * 128 + (uint32_t)((q ^ (i & 7)) << 4);
            *(uint4*)(smem + S_BHI + off) = qhv;
            *(uint4*)(smem + S_BLO + off) = qlv;
        }
    } else if (tid < 64) {
        // ---- ET table: {u_i, v_i, b1_i, 0} ----
        const int c = tid;
        ((float4*)(smem + S_ET))[c] =
            make_float4(W1[64 * 64 + c], W1[64 * 64 + 64 + c], b1[c], 0.f);
    }
    __syncthreads();

    // ---- GEMM1: warp wid owns pixel rows [16*wid, 16*wid+16) ----
    float dacc[8][4];
    #pragma unroll
    for (int nt = 0; nt < 8; nt++)
        #pragma unroll
        for (int r = 0; r < 4; r++) dacc[nt][r] = 0.f;

    {
        const int m0w = 16 * wid;
        const int rl  = lane & 15;
        const int qhh = lane >> 4;
        const int rx  = lane & 7;

        #pragma unroll
        for (int term = 0; term < 3; term++) {
            const uint32_t SA = sb + (term == 1 ? S_ALO : S_AHI);
            const uint32_t SB = sb + (term == 2 ? S_BLO : S_BHI);
            #pragma unroll
            for (int kt = 0; kt < 4; kt++) {
                const uint32_t kx = (uint32_t)(((2 * kt + qhh) ^ rx) << 4);
                uint32_t a0[4];
                ldsm4(SA + (uint32_t)(m0w + rl) * 128 + kx, a0[0], a0[1], a0[2], a0[3]);
                #pragma unroll
                for (int ntp = 0; ntp < 4; ntp++) {
                    uint32_t r0, r1, r2, r3;
                    ldsm4(SB + (uint32_t)(16 * ntp + rl) * 128 + kx, r0, r1, r2, r3);
                    mma_bf16(dacc[2 * ntp],     a0, r0, r2);
                    mma_bf16(dacc[2 * ntp + 1], a0, r1, r3);
                }
            }
        }
    }
    __syncthreads();   // all ldmatrix reads done before base16_s overwrites A

    // ---- D fragments -> base16_s[px][pair] as f16x2 (cvt ONCE) ----
    uint32_t* base16 = (uint32_t*)smem;
    {
        const int g = lane >> 2, tg0 = lane & 3;
        const int m = 16 * wid + g;
        #pragma unroll
        for (int nt = 0; nt < 8; nt++) {
            const int pidx = nt * 4 + tg0;           // pair index = col/2
            base16[m * HSTR + pidx]       = f16x2of(dacc[nt][0], dacc[nt][1]);
            base16[(m + 8) * HSTR + pidx] = f16x2of(dacc[nt][2], dacc[nt][3]);
        }
    }
    __syncthreads();

    // ==== GEMM2: per px, out[16 jk, 8ch] = relu(H)[16,64] @ W2 ====
    const int tg   = lane & 3;
    const int row0 = lane >> 2;            // jk row (j = row>>2, k = row&3)
    const int j0   = row0 >> 2;
    const int k0i  = row0 & 3;
    const float rj = -0.75f + 0.5f * (float)j0;
    const float rk = -0.75f + 0.5f * (float)k0i;

    // ajbk constants as f16x2, rows row0 (ajbk0h) and row0+8 (ajbk1h)
    const float4* ET4 = (const float4*)(smem + S_ET);
    uint32_t ajbk0h[8], ajbk1h[8];
    #pragma unroll
    for (int p = 0; p < 8; p++) {
        const int i0 = (p >> 1) * 16 + (p & 1) * 8 + 2 * tg;
        const float4 ea = ET4[i0];
        const float4 eb = ET4[i0 + 1];
        const float f0 = fmaf(rj, ea.x, fmaf(rk, ea.y, ea.z));
        const float f1 = fmaf(rj, eb.x, fmaf(rk, eb.y, eb.z));
        ajbk0h[p] = f16x2of(f0, f1);
        ajbk1h[p] = f16x2of(f0 + ea.x, f1 + eb.x);   // j+2 -> rel_j + 1
    }

    // W2 fp16 B-fragments (col n = lane>>2; valid n < 3)
    const int nn = lane >> 2;
    const bool nv = nn < 3;
    uint32_t bw[4][2];
    #pragma unroll
    for (int kt = 0; kt < 4; kt++) {
        #pragma unroll
        for (int hh = 0; hh < 2; hh++) {
            const int kk = kt * 16 + 2 * tg + hh * 8;
            const float w0 = nv ? W2[kk * 3 + nn] : 0.f;
            const float w1 = nv ? W2[(kk + 1) * 3 + nn] : 0.f;
            bw[kt][hh] = f16x2of(w0, w1);
        }
    }

    const int ch0 = 2 * tg, ch1 = 2 * tg + 1;
    const float bb0 = (ch0 < 3) ? b2[ch0] : 0.f;
    const float bb1 = (ch1 < 3) ? b2[ch1] : 0.f;

    #pragma unroll 4
    for (int t16 = 0; t16 < 16; t16++) {
        const int px = 16 * wid + t16;
        const uint32_t* bp16 = base16 + px * HSTR;
        float C[4] = {0.f, 0.f, 0.f, 0.f};
        #pragma unroll
        for (int kt = 0; kt < 4; kt++) {
            const uint32_t bp0 = bp16[kt * 8 + tg];       // i = 16kt + 2tg
            const uint32_t bp1 = bp16[kt * 8 + 4 + tg];   // i = 16kt + 8 + 2tg
            uint32_t a[4];
            a[0] = hmax2z(hadd2(bp0, ajbk0h[kt * 2]));
            a[1] = hmax2z(hadd2(bp0, ajbk1h[kt * 2]));
            a[2] = hmax2z(hadd2(bp1, ajbk0h[kt * 2 + 1]));
            a[3] = hmax2z(hadd2(bp1, ajbk1h[kt * 2 + 1]));
            mma_f16(C, a, bw[kt][0], bw[kt][1]);
        }
        // stores: rows (j0, k0i) and (j0+2, k0i); cols ch0, ch1
        const int xx = 4 * px + k0i;
        if (ch0 < 3) {
            out[((size_t)(b * 3 + ch0) * OUT + 4 * h + j0) * OUT + xx]       = C[0] + bb0;
            out[((size_t)(b * 3 + ch0) * OUT + 4 * h + j0 + 2) * OUT + xx]   = C[2] + bb0;
        }
        if (ch1 < 3) {
            out[((size_t)(b * 3 + ch1) * OUT + 4 * h + j0) * OUT + xx]       = C[1] + bb1;
            out[((size_t)(b * 3 + ch1) * OUT + 4 * h + j0 + 2) * OUT + xx]   = C[3] + bb1;
        }
    }
}

}  // namespace

extern "C" void kernel_launch(void* const* d_in, const int* in_sizes, int n_in,
                              void* d_out, int out_size) {
    const float* x  = (const float*)d_in[0];
    const float* W1 = (const float*)d_in[1];
    const float* b1 = (const float*)d_in[2];
    const float* W2 = (const float*)d_in[3];
    const float* b2 = (const float*)d_in[4];
    float* out = (float*)d_out;

    cudaFuncSetAttribute(mlp_interp_mma,
                         cudaFuncAttributeMaxDynamicSharedMemorySize, S_TOTAL);
    mlp_interp_mma<<<512, 256, S_TOTAL>>>(x, W1, b1, W2, b2, out);
}

// round 17
// speedup vs baseline: 1.2122x; 1.0977x over previous
#include <cuda_runtime.h>
#include <cuda_bf16.h>
#include <cstdint>
#include <cstring>

// MLP_Interpolate: 4x nearest upsample + 2-layer MLP. SINGLE LAUNCH.
// GEMM1 (base = X @ W1[0:64]^T): tensor pipe, bf16 3-term split (~1.5e-5),
//   kt-major fragment hoisting: each A/B ldsm issued exactly once (72->40).
// GEMM2 (out = relu(H) @ W2): tensor pipe fp16, H carried fp16 end-to-end;
//   base16 pair-interleaved so each kt needs one LDS.64 (128->64 LDS).

namespace {

typedef unsigned long long ull;

__device__ __forceinline__ uint32_t s2u(const void* p) {
    uint32_t a;
    asm("{ .reg .u64 t; cvta.to.shared.u64 t, %1; cvt.u32.u64 %0, t; }" : "=r"(a) : "l"(p));
    return a;
}
__device__ __forceinline__ uint32_t f16x2of(float lo, float hi) {
    uint32_t r;
    asm("cvt.rn.f16x2.f32 %0, %1, %2;" : "=r"(r) : "f"(hi), "f"(lo));
    return r;
}
__device__ __forceinline__ uint32_t hadd2(uint32_t a, uint32_t b) {
    uint32_t d; asm("add.rn.f16x2 %0, %1, %2;" : "=r"(d) : "r"(a), "r"(b)); return d;
}
__device__ __forceinline__ uint32_t hmax2z(uint32_t a) {
    uint32_t d; asm("max.f16x2 %0, %1, %2;" : "=r"(d) : "r"(a), "r"(0u)); return d;
}
__device__ __forceinline__ void ldsm4(uint32_t addr, uint32_t& r0, uint32_t& r1,
                                      uint32_t& r2, uint32_t& r3) {
    asm volatile("ldmatrix.sync.aligned.m8n8.x4.shared.b16 {%0,%1,%2,%3}, [%4];"
                 : "=r"(r0), "=r"(r1), "=r"(r2), "=r"(r3) : "r"(addr));
}
__device__ __forceinline__ void mma_bf16(float* d, const uint32_t* a,
                                         uint32_t b0, uint32_t b1) {
    asm volatile(
        "mma.sync.aligned.m16n8k16.row.col.f32.bf16.bf16.f32 "
        "{%0,%1,%2,%3}, {%4,%5,%6,%7}, {%8,%9}, {%0,%1,%2,%3};"
        : "+f"(d[0]), "+f"(d[1]), "+f"(d[2]), "+f"(d[3])
        : "r"(a[0]), "r"(a[1]), "r"(a[2]), "r"(a[3]), "r"(b0), "r"(b1));
}
__device__ __forceinline__ void mma_f16(float* d, const uint32_t* a,
                                        uint32_t b0, uint32_t b1) {
    asm volatile(
        "mma.sync.aligned.m16n8k16.row.col.f32.f16.f16.f32 "
        "{%0,%1,%2,%3}, {%4,%5,%6,%7}, {%8,%9}, {%0,%1,%2,%3};"
        : "+f"(d[0]), "+f"(d[1]), "+f"(d[2]), "+f"(d[3])
        : "r"(a[0]), "r"(a[1]), "r"(a[2]), "r"(a[3]), "r"(b0), "r"(b1));
}

constexpr int Hh = 128, Wd = 128, HW = Hh * Wd, OUT = 512;
constexpr int HSTR = 34;   // base16_s row stride in uint32 (f16x2 pairs)

// smem layout (bytes).
// Staging: A (0..32768), B (32768..49152), ET (49152..50176).
// Post-GEMM1: base16_s [128][34] uint32 (17408 B) overlays dead A region.
constexpr int S_AHI = 0;            // X_hi  [128][64 bf16]  16384
constexpr int S_ALO = 16384;        // X_lo                  16384
constexpr int S_BHI = 32768;        // W1T_hi [64][64 bf16]   8192
constexpr int S_BLO = 40960;        // W1T_lo                 8192
constexpr int S_ET  = 49152;        // ET4[64] float4 {u,v,b1,0} 1024
constexpr int S_TOTAL = 50176;

// split 8 floats -> bf16-hi quad + bf16-lo quad
__device__ __forceinline__ void pack8(const float* v, uint4& qh, uint4& ql) {
    uint32_t H[4], L[4];
    #pragma unroll
    for (int p = 0; p < 4; p++) {
        uint32_t hp;
        asm("cvt.rn.bf16x2.f32 %0, %1, %2;" : "=r"(hp) : "f"(v[2*p+1]), "f"(v[2*p]));
        const float h0 = __uint_as_float(hp << 16);
        const float h1 = __uint_as_float(hp & 0xffff0000u);
        const float l0 = v[2*p]   - h0;
        const float l1 = v[2*p+1] - h1;
        uint32_t lp;
        asm("cvt.rn.bf16x2.f32 %0, %1, %2;" : "=r"(lp) : "f"(l1), "f"(l0));
        H[p] = hp; L[p] = lp;
    }
    qh = make_uint4(H[0], H[1], H[2], H[3]);
    ql = make_uint4(L[0], L[1], L[2], L[3]);
}

__global__ __launch_bounds__(256, 3)
void mlp_interp_mma(const float* __restrict__ x, const float* __restrict__ W1,
                    const float* __restrict__ b1, const float* __restrict__ W2,
                    const float* __restrict__ b2, float* __restrict__ out)
{
    extern __shared__ char smem[];
    const uint32_t sb = s2u(smem);
    const int tid  = threadIdx.x;
    const int lane = tid & 31;
    const int wid  = tid >> 5;            // 0..7
    const int pxs  = tid >> 1;            // staging pixel 0..127
    const int shalf = tid & 1;            // staging channel half
    const int cta  = blockIdx.x;          // 512: (b, h)
    const int h = cta & (Hh - 1);
    const int b = cta >> 7;

    // ---- stage A: thread (pxs, shalf) packs channels [32s, 32s+32) ----
    {
        const float* xp = x + ((size_t)b * 64 + 32 * shalf) * HW + h * Wd + pxs;
        #pragma unroll
        for (int qq = 0; qq < 4; qq++) {
            float v[8];
            #pragma unroll
            for (int c = 0; c < 8; c++) v[c] = xp[(size_t)(8 * qq + c) * HW];
            uint4 qhv, qlv;
            pack8(v, qhv, qlv);
            const int q = 4 * shalf + qq;
            const uint32_t off = (uint32_t)pxs * 128 + (uint32_t)((q ^ (pxs & 7)) << 4);
            *(uint4*)(smem + S_AHI + off) = qhv;
            *(uint4*)(smem + S_ALO + off) = qlv;
        }
    }

    if (tid >= 128) {
        // ---- stage B: thread (i, s2) packs W1[32s2..32s2+32][i] ----
        const int t2 = tid - 128;
        const int i  = t2 >> 1;
        const int s2 = t2 & 1;
        #pragma unroll
        for (int qq = 0; qq < 4; qq++) {
            float v[8];
            #pragma unroll
            for (int c = 0; c < 8; c++) v[c] = W1[(32 * s2 + 8 * qq + c) * 64 + i];
            uint4 qhv, qlv;
            pack8(v, qhv, qlv);
            const int q = 4 * s2 + qq;
            const uint32_t off = (uint32_t)i * 128 + (uint32_t)((q ^ (i & 7)) << 4);
            *(uint4*)(smem + S_BHI + off) = qhv;
            *(uint4*)(smem + S_BLO + off) = qlv;
        }
    } else if (tid < 64) {
        // ---- ET table: {u_i, v_i, b1_i, 0} ----
        const int c = tid;
        ((float4*)(smem + S_ET))[c] =
            make_float4(W1[64 * 64 + c], W1[64 * 64 + 64 + c], b1[c], 0.f);
    }
    __syncthreads();

    // ---- GEMM1 (kt-major, each fragment loaded once) ----
    float dacc[8][4];
    #pragma unroll
    for (int nt = 0; nt < 8; nt++)
        #pragma unroll
        for (int r = 0; r < 4; r++) dacc[nt][r] = 0.f;

    {
        const int m0w = 16 * wid;
        const int rl  = lane & 15;
        const int qhh = lane >> 4;
        const int rx  = lane & 7;

        #pragma unroll
        for (int kt = 0; kt < 4; kt++) {
            const uint32_t kx = (uint32_t)(((2 * kt + qhh) ^ rx) << 4);
            const uint32_t arow = (uint32_t)(m0w + rl) * 128 + kx;
            uint32_t ah[4], al[4];
            ldsm4(sb + S_AHI + arow, ah[0], ah[1], ah[2], ah[3]);
            ldsm4(sb + S_ALO + arow, al[0], al[1], al[2], al[3]);
            #pragma unroll
            for (int ntp = 0; ntp < 4; ntp++) {
                const uint32_t brow = (uint32_t)(16 * ntp + rl) * 128 + kx;
                uint32_t b0, b1v, b2v, b3;
                ldsm4(sb + S_BHI + brow, b0, b1v, b2v, b3);
                mma_bf16(dacc[2 * ntp],     ah, b0, b2v);
                mma_bf16(dacc[2 * ntp + 1], ah, b1v, b3);
                mma_bf16(dacc[2 * ntp],     al, b0, b2v);
                mma_bf16(dacc[2 * ntp + 1], al, b1v, b3);
                ldsm4(sb + S_BLO + brow, b0, b1v, b2v, b3);
                mma_bf16(dacc[2 * ntp],     ah, b0, b2v);
                mma_bf16(dacc[2 * ntp + 1], ah, b1v, b3);
            }
        }
    }
    __syncthreads();   // all ldmatrix reads done before base16_s overwrites A

    // ---- D fragments -> base16_s as f16x2 (cvt ONCE), pair-interleaved:
    //      pair (i/2) with kt=i>>4, hh=(i>>3)&1, tg=(i>>1)&3 at pos 8kt+2tg+hh
    uint32_t* base16 = (uint32_t*)smem;
    {
        const int g = lane >> 2, tg0 = lane & 3;
        const int m = 16 * wid + g;
        #pragma unroll
        for (int nt = 0; nt < 8; nt++) {
            const int pidx = 8 * (nt >> 1) + 2 * tg0 + (nt & 1);
            base16[m * HSTR + pidx]       = f16x2of(dacc[nt][0], dacc[nt][1]);
            base16[(m + 8) * HSTR + pidx] = f16x2of(dacc[nt][2], dacc[nt][3]);
        }
    }
    __syncthreads();

    // ==== GEMM2: per px, out[16 jk, 8ch] = relu(H)[16,64] @ W2 ====
    const int tg   = lane & 3;
    const int row0 = lane >> 2;            // jk row (j = row>>2, k = row&3)
    const int j0   = row0 >> 2;
    const int k0i  = row0 & 3;
    const float rj = -0.75f + 0.5f * (float)j0;
    const float rk = -0.75f + 0.5f * (float)k0i;

    // ajbk constants as f16x2, rows row0 (ajbk0h) and row0+8 (ajbk1h)
    const float4* ET4 = (const float4*)(smem + S_ET);
    uint32_t ajbk0h[8], ajbk1h[8];
    #pragma unroll
    for (int p = 0; p < 8; p++) {
        const int i0 = (p >> 1) * 16 + (p & 1) * 8 + 2 * tg;
        const float4 ea = ET4[i0];
        const float4 eb = ET4[i0 + 1];
        const float f0 = fmaf(rj, ea.x, fmaf(rk, ea.y, ea.z));
        const float f1 = fmaf(rj, eb.x, fmaf(rk, eb.y, eb.z));
        ajbk0h[p] = f16x2of(f0, f1);
        ajbk1h[p] = f16x2of(f0 + ea.x, f1 + eb.x);   // j+2 -> rel_j + 1
    }

    // W2 fp16 B-fragments (col n = lane>>2; valid n < 3)
    const int nn = lane >> 2;
    const bool nv = nn < 3;
    uint32_t bw[4][2];
    #pragma unroll
    for (int kt = 0; kt < 4; kt++) {
        #pragma unroll
        for (int hh = 0; hh < 2; hh++) {
            const int kk = kt * 16 + 2 * tg + hh * 8;
            const float w0 = nv ? W2[kk * 3 + nn] : 0.f;
            const float w1 = nv ? W2[(kk + 1) * 3 + nn] : 0.f;
            bw[kt][hh] = f16x2of(w0, w1);
        }
    }

    const int ch0 = 2 * tg, ch1 = 2 * tg + 1;
    const float bb0 = (ch0 < 3) ? b2[ch0] : 0.f;
    const float bb1 = (ch1 < 3) ? b2[ch1] : 0.f;

    #pragma unroll 4
    for (int t16 = 0; t16 < 16; t16++) {
        const int px = 16 * wid + t16;
        const uint32_t* bp16 = base16 + px * HSTR + 2 * tg;
        float C[4] = {0.f, 0.f, 0.f, 0.f};
        #pragma unroll
        for (int kt = 0; kt < 4; kt++) {
            const uint2 bp = *(const uint2*)(bp16 + kt * 8);   // (hh=0, hh=1)
            uint32_t a[4];
            a[0] = hmax2z(hadd2(bp.x, ajbk0h[kt * 2]));
            a[1] = hmax2z(hadd2(bp.x, ajbk1h[kt * 2]));
            a[2] = hmax2z(hadd2(bp.y, ajbk0h[kt * 2 + 1]));
            a[3] = hmax2z(hadd2(bp.y, ajbk1h[kt * 2 + 1]));
            mma_f16(C, a, bw[kt][0], bw[kt][1]);
        }
        // stores: rows (j0, k0i) and (j0+2, k0i); cols ch0, ch1
        const int xx = 4 * px + k0i;
        if (ch0 < 3) {
            out[((size_t)(b * 3 + ch0) * OUT + 4 * h + j0) * OUT + xx]       = C[0] + bb0;
            out[((size_t)(b * 3 + ch0) * OUT + 4 * h + j0 + 2) * OUT + xx]   = C[2] + bb0;
        }
        if (ch1 < 3) {
            out[((size_t)(b * 3 + ch1) * OUT + 4 * h + j0) * OUT + xx]       = C[1] + bb1;
            out[((size_t)(b * 3 + ch1) * OUT + 4 * h + j0 + 2) * OUT + xx]   = C[3] + bb1;
        }
    }
}

}  // namespace

extern "C" void kernel_launch(void* const* d_in, const int* in_sizes, int n_in,
                              void* d_out, int out_size) {
    const float* x  = (const float*)d_in[0];
    const float* W1 = (const float*)d_in[1];
    const float* b1 = (const float*)d_in[2];
    const float* W2 = (const float*)d_in[3];
    const float* b2 = (const float*)d_in[4];
    float* out = (float*)d_out;

    cudaFuncSetAttribute(mlp_interp_mma,
                         cudaFuncAttributeMaxDynamicSharedMemorySize, S_TOTAL);
    mlp_interp_mma<<<512, 256, S_TOTAL>>>(x, W1, b1, W2, b2, out);
}